// round 3
// baseline (speedup 1.0000x reference)
#include <cuda_runtime.h>
#include <cstdint>
#include <math_constants.h>

#define LOG2E 1.4426950408889634f

typedef unsigned long long u64;

// Scratch: 16 m-chunks x (8*4096) n's: partial sumE, partial sum(E*d'), partial max d'.
__device__ float g_partE[16 * 32768];
__device__ float g_partT[16 * 32768];
__device__ float g_partM[16 * 32768];

__device__ __forceinline__ u64 f2fma(u64 a, u64 b, u64 c) {
    u64 r; asm("fma.rn.f32x2 %0,%1,%2,%3;" : "=l"(r) : "l"(a), "l"(b), "l"(c)); return r;
}
__device__ __forceinline__ u64 f2add(u64 a, u64 b) {
    u64 r; asm("add.rn.f32x2 %0,%1,%2;" : "=l"(r) : "l"(a), "l"(b)); return r;
}
__device__ __forceinline__ u64 pk(float lo, float hi) {
    u64 r; asm("mov.b64 %0,{%1,%2};" : "=l"(r) : "f"(lo), "f"(hi)); return r;
}
__device__ __forceinline__ void up(u64 v, float& lo, float& hi) {
    asm("mov.b64 {%0,%1},%2;" : "=f"(lo), "=f"(hi) : "l"(v));
}
__device__ __forceinline__ float ex2f(float x) {
    float r; asm("ex2.approx.f32 %0,%1;" : "=f"(r) : "f"(x)); return r;
}

__global__ void zero_out_kernel(float* out) { *out = 0.0f; }

// B=8, N=4096, M=4096, D=3 hardcoded.
// Grid: 1024 blocks = 8 batches x 8 n-chunks x 16 m-chunks.
// Block: 256 threads; each thread owns 2 n's; block owns 256 m's.
__global__ void __launch_bounds__(256) fape_main_kernel(
    const float* __restrict__ Xp,   // (8,4096,3)
    const float* __restrict__ Xt,   // (8,4096,3)
    const float* __restrict__ Rp,   // (8,3,3)
    const float* __restrict__ tp,   // (8,3)
    const float* __restrict__ Rt,   // (8,3,3)
    const float* __restrict__ tt,   // (8,3)
    const float* __restrict__ temp) // (1,)
{
    // 128 m-pair groups x 4 packed u64: [vx01, vy01, vz01, vw01] per group.
    __shared__ __align__(16) u64 sm[128 * 4];   // 4 KB

    const int mchunk = blockIdx.x & 15;
    const int nchunk = (blockIdx.x >> 4) & 7;
    const int b      = blockIdx.x >> 7;
    const int tid    = threadIdx.x;

    const float T = *temp;
    const float s = -LOG2E / T;   // logit scale in log2 domain (s < 0)

    // ---- Fill smem: v = (s*-2*Xt', s*|Xt'|^2) for this block's 256 m's ----
    {
        const float* R  = Rt + b * 9;
        const float* tv = tt + b * 3;
        const float r00 = R[0], r01 = R[1], r02 = R[2];
        const float r10 = R[3], r11 = R[4], r12 = R[5];
        const float r20 = R[6], r21 = R[7], r22 = R[8];
        const float tx = tv[0], ty = tv[1], tz = tv[2];
        const float s2 = s * -2.0f;

        const int mi = tid;   // one m per thread
        const float* xm = Xt + (size_t)(b * 4096 + mchunk * 256 + mi) * 3;
        const float x = xm[0], y = xm[1], z = xm[2];
        const float ax = r00 * x + r01 * y + r02 * z + tx;
        const float ay = r10 * x + r11 * y + r12 * z + ty;
        const float az = r20 * x + r21 * y + r22 * z + tz;
        const float sq = ax * ax + ay * ay + az * az;
        const int j = mi >> 1, h = mi & 1;
        float* w = (float*)(sm + j * 4);
        w[0 + h] = s2 * ax;   // vx
        w[2 + h] = s2 * ay;   // vy
        w[4 + h] = s2 * az;   // vz
        w[6 + h] = s * sq;    // vw
    }

    // ---- Per-thread: two n's ----
    const float* Rq = Rp + b * 9;
    const float* tq = tp + b * 3;
    const float q00 = Rq[0], q01 = Rq[1], q02 = Rq[2];
    const float q10 = Rq[3], q11 = Rq[4], q12 = Rq[5];
    const float q20 = Rq[6], q21 = Rq[7], q22 = Rq[8];
    const float u0 = tq[0], u1 = tq[1], u2 = tq[2];

    const int n0 = nchunk * 512 + tid;      // and n1 = n0 + 256
    const float* xa = Xp + (size_t)(b * 4096 + n0) * 3;
    const float* xb = xa + 256 * 3;

    const float ax0 = xa[0], ay0 = xa[1], az0 = xa[2];
    const float px0 = q00 * ax0 + q01 * ay0 + q02 * az0 + u0;
    const float py0 = q10 * ax0 + q11 * ay0 + q12 * az0 + u1;
    const float pz0 = q20 * ax0 + q21 * ay0 + q22 * az0 + u2;
    const float sc0 = s * (px0 * px0 + py0 * py0 + pz0 * pz0);

    const float ax1 = xb[0], ay1 = xb[1], az1 = xb[2];
    const float px1 = q00 * ax1 + q01 * ay1 + q02 * az1 + u0;
    const float py1 = q10 * ax1 + q11 * ay1 + q12 * az1 + u1;
    const float pz1 = q20 * ax1 + q21 * ay1 + q22 * az1 + u2;
    const float sc1 = s * (px1 * px1 + py1 * py1 + pz1 * pz1);

    const u64 Px0 = pk(px0, px0), Py0 = pk(py0, py0), Pz0 = pk(pz0, pz0), Sc0 = pk(sc0, sc0);
    const u64 Px1 = pk(px1, px1), Py1 = pk(py1, py1), Pz1 = pk(pz1, pz1), Sc1 = pk(sc1, sc1);

    u64 Se0 = 0ull, St0 = 0ull;   // packed (0.0f, 0.0f)
    u64 Se1 = 0ull, St1 = 0ull;
    float mxA = -CUDART_INF_F, mxB = -CUDART_INF_F;

    __syncthreads();

    #pragma unroll 8
    for (int j = 0; j < 128; j++) {
        const ulonglong2 v1 = *(const ulonglong2*)(sm + j * 4);     // vx, vy
        const ulonglong2 v2 = *(const ulonglong2*)(sm + j * 4 + 2); // vz, vw

        // n0 chain
        u64 d0 = f2add(Sc0, v2.y);
        d0 = f2fma(Pz0, v2.x, d0);
        d0 = f2fma(Py0, v1.y, d0);
        d0 = f2fma(Px0, v1.x, d0);
        // n1 chain (independent)
        u64 d1 = f2add(Sc1, v2.y);
        d1 = f2fma(Pz1, v2.x, d1);
        d1 = f2fma(Py1, v1.y, d1);
        d1 = f2fma(Px1, v1.x, d1);

        float a0, b0, a1, b1;
        up(d0, a0, b0);
        up(d1, a1, b1);
        mxA = fmaxf(mxA, fmaxf(a0, b0));    // ALU pipe
        mxB = fmaxf(mxB, fmaxf(a1, b1));
        const u64 E0 = pk(ex2f(a0), ex2f(b0));
        const u64 E1 = pk(ex2f(a1), ex2f(b1));
        Se0 = f2add(Se0, E0);
        St0 = f2fma(E0, d0, St0);
        Se1 = f2add(Se1, E1);
        St1 = f2fma(E1, d1, St1);
    }

    // Write partials: one writer per (n, mchunk)
    float e0, e1, t0, t1;
    const int gbase = mchunk * 32768 + b * 4096 + nchunk * 512 + tid;
    up(Se0, e0, e1); up(St0, t0, t1);
    g_partE[gbase] = e0 + e1;
    g_partT[gbase] = t0 + t1;
    g_partM[gbase] = mxA;
    up(Se1, e0, e1); up(St1, t0, t1);
    g_partE[gbase + 256] = e0 + e1;
    g_partT[gbase + 256] = t0 + t1;
    g_partM[gbase + 256] = mxB;
}

// Combine 16 m-chunk partials per n; rare shifted-recompute fallback when the
// unshifted exp sums fully underflowed; reduce to the global mean.
__global__ void __launch_bounds__(256) fape_reduce_kernel(
    const float* __restrict__ Xp,
    const float* __restrict__ Xt,
    const float* __restrict__ Rp,
    const float* __restrict__ tp,
    const float* __restrict__ Rt,
    const float* __restrict__ tt,
    const float* __restrict__ temp,
    float* __restrict__ out)
{
    const int idx = blockIdx.x * 256 + threadIdx.x;   // 0..32767 == b*4096 + n
    float sE = 0.0f, sT = 0.0f, M = -CUDART_INF_F;
    #pragma unroll
    for (int c = 0; c < 16; c++) {
        sE += g_partE[c * 32768 + idx];
        sT += g_partT[c * 32768 + idx];
        M = fmaxf(M, g_partM[c * 32768 + idx]);
    }
    const float T = *temp;
    const float s = -LOG2E / T;
    const float invs = 1.0f / s;

    float weighted;
    if (sE > 1e-20f) {
        weighted = invs * (sT / sE);
    } else {
        // All (or nearly all) exps underflowed: recompute shifted by the max logit M.
        const int b = idx >> 12;
        const float* Rq = Rp + b * 9;
        const float* tq = tp + b * 3;
        const float* xpn = Xp + (size_t)idx * 3;
        const float qx = xpn[0], qy = xpn[1], qz = xpn[2];
        const float px = Rq[0] * qx + Rq[1] * qy + Rq[2] * qz + tq[0];
        const float py = Rq[3] * qx + Rq[4] * qy + Rq[5] * qz + tq[1];
        const float pz = Rq[6] * qx + Rq[7] * qy + Rq[8] * qz + tq[2];
        const float base = s * (px * px + py * py + pz * pz) - M;

        const float* R  = Rt + b * 9;
        const float* tv = tt + b * 3;
        const float r00 = R[0], r01 = R[1], r02 = R[2];
        const float r10 = R[3], r11 = R[4], r12 = R[5];
        const float r20 = R[6], r21 = R[7], r22 = R[8];
        const float tx = tv[0], ty = tv[1], tz = tv[2];
        const float s2 = s * -2.0f;
        const float* xtb = Xt + (size_t)b * 4096 * 3;

        float e2 = 0.0f, t2 = 0.0f;
        for (int m = 0; m < 4096; m++) {
            const float x = xtb[m * 3 + 0], y = xtb[m * 3 + 1], z = xtb[m * 3 + 2];
            const float ax = r00 * x + r01 * y + r02 * z + tx;
            const float ay = r10 * x + r11 * y + r12 * z + ty;
            const float az = r20 * x + r21 * y + r22 * z + tz;
            const float sq = ax * ax + ay * ay + az * az;
            const float t = base + s * sq + s2 * (px * ax + py * ay + pz * az);
            const float e = ex2f(t);   // t <= ~0 by construction (shifted by max)
            e2 += e;
            t2 += e * t;
        }
        weighted = invs * (t2 / e2 + M);
    }

    __shared__ float red[256];
    red[threadIdx.x] = weighted;
    __syncthreads();
    #pragma unroll
    for (int off = 128; off > 0; off >>= 1) {
        if (threadIdx.x < off) red[threadIdx.x] += red[threadIdx.x + off];
        __syncthreads();
    }
    if (threadIdx.x == 0)
        atomicAdd(out, red[0] * (1.0f / (8.0f * 4096.0f)));
}

extern "C" void kernel_launch(void* const* d_in, const int* in_sizes, int n_in,
                              void* d_out, int out_size) {
    const float* Xp   = (const float*)d_in[0];
    const float* Xt   = (const float*)d_in[1];
    const float* Rp   = (const float*)d_in[2];
    const float* tp   = (const float*)d_in[3];
    const float* Rt   = (const float*)d_in[4];
    const float* tt   = (const float*)d_in[5];
    const float* temp = (const float*)d_in[6];
    float* out = (float*)d_out;

    zero_out_kernel<<<1, 1>>>(out);
    fape_main_kernel<<<1024, 256>>>(Xp, Xt, Rp, tp, Rt, tt, temp);
    fape_reduce_kernel<<<128, 256>>>(Xp, Xt, Rp, tp, Rt, tt, temp, out);
}

// round 4
// speedup vs baseline: 1.5012x; 1.5012x over previous
#include <cuda_runtime.h>
#include <cstdint>
#include <math_constants.h>

#define LOG2E 1.4426950408889634f

typedef unsigned long long u64;

// Scratch: 16 m-chunks x (8*4096) n's: partial sumE, partial sum(E*d').
__device__ float g_partE[16 * 32768];
__device__ float g_partT[16 * 32768];

__device__ __forceinline__ u64 f2fma(u64 a, u64 b, u64 c) {
    u64 r; asm("fma.rn.f32x2 %0,%1,%2,%3;" : "=l"(r) : "l"(a), "l"(b), "l"(c)); return r;
}
__device__ __forceinline__ u64 f2add(u64 a, u64 b) {
    u64 r; asm("add.rn.f32x2 %0,%1,%2;" : "=l"(r) : "l"(a), "l"(b)); return r;
}
__device__ __forceinline__ u64 pk(float lo, float hi) {
    u64 r; asm("mov.b64 %0,{%1,%2};" : "=l"(r) : "f"(lo), "f"(hi)); return r;
}
__device__ __forceinline__ void up(u64 v, float& lo, float& hi) {
    asm("mov.b64 {%0,%1},%2;" : "=f"(lo), "=f"(hi) : "l"(v));
}
__device__ __forceinline__ float ex2f(float x) {
    float r; asm("ex2.approx.f32 %0,%1;" : "=f"(r) : "f"(x)); return r;
}

__global__ void zero_out_kernel(float* out) { *out = 0.0f; }

// B=8, N=4096, M=4096, D=3 hardcoded.
// Grid: 1024 blocks = 8 batches x 8 n-chunks x 16 m-chunks.
// Block: 256 threads; each thread owns 2 n's; block owns 256 m's.
__global__ void __launch_bounds__(256) fape_main_kernel(
    const float* __restrict__ Xp,   // (8,4096,3)
    const float* __restrict__ Xt,   // (8,4096,3)
    const float* __restrict__ Rp,   // (8,3,3)
    const float* __restrict__ tp,   // (8,3)
    const float* __restrict__ Rt,   // (8,3,3)
    const float* __restrict__ tt,   // (8,3)
    const float* __restrict__ temp) // (1,)
{
    // 128 m-pair groups x 4 packed u64: [vx01, vy01, vz01, vw01] per group.
    __shared__ __align__(16) u64 sm[128 * 4];   // 4 KB

    const int mchunk = blockIdx.x & 15;
    const int nchunk = (blockIdx.x >> 4) & 7;
    const int b      = blockIdx.x >> 7;
    const int tid    = threadIdx.x;

    const float T = *temp;
    const float s = -LOG2E / T;   // logit scale in log2 domain (s < 0)

    // ---- Fill smem: v = (s*-2*Xt', s*|Xt'|^2) for this block's 256 m's ----
    {
        const float* R  = Rt + b * 9;
        const float* tv = tt + b * 3;
        const float r00 = R[0], r01 = R[1], r02 = R[2];
        const float r10 = R[3], r11 = R[4], r12 = R[5];
        const float r20 = R[6], r21 = R[7], r22 = R[8];
        const float tx = tv[0], ty = tv[1], tz = tv[2];
        const float s2 = s * -2.0f;

        const int mi = tid;   // one m per thread
        const float* xm = Xt + (size_t)(b * 4096 + mchunk * 256 + mi) * 3;
        const float x = xm[0], y = xm[1], z = xm[2];
        const float ax = r00 * x + r01 * y + r02 * z + tx;
        const float ay = r10 * x + r11 * y + r12 * z + ty;
        const float az = r20 * x + r21 * y + r22 * z + tz;
        const float sq = ax * ax + ay * ay + az * az;
        const int j = mi >> 1, h = mi & 1;
        float* w = (float*)(sm + j * 4);
        w[0 + h] = s2 * ax;   // vx
        w[2 + h] = s2 * ay;   // vy
        w[4 + h] = s2 * az;   // vz
        w[6 + h] = s * sq;    // vw
    }

    // ---- Per-thread: two n's ----
    const float* Rq = Rp + b * 9;
    const float* tq = tp + b * 3;
    const float q00 = Rq[0], q01 = Rq[1], q02 = Rq[2];
    const float q10 = Rq[3], q11 = Rq[4], q12 = Rq[5];
    const float q20 = Rq[6], q21 = Rq[7], q22 = Rq[8];
    const float u0 = tq[0], u1 = tq[1], u2 = tq[2];

    const int n0 = nchunk * 512 + tid;      // and n1 = n0 + 256
    const float* xa = Xp + (size_t)(b * 4096 + n0) * 3;
    const float* xb = xa + 256 * 3;

    const float ax0 = xa[0], ay0 = xa[1], az0 = xa[2];
    const float px0 = q00 * ax0 + q01 * ay0 + q02 * az0 + u0;
    const float py0 = q10 * ax0 + q11 * ay0 + q12 * az0 + u1;
    const float pz0 = q20 * ax0 + q21 * ay0 + q22 * az0 + u2;
    const float sc0 = s * (px0 * px0 + py0 * py0 + pz0 * pz0);

    const float ax1 = xb[0], ay1 = xb[1], az1 = xb[2];
    const float px1 = q00 * ax1 + q01 * ay1 + q02 * az1 + u0;
    const float py1 = q10 * ax1 + q11 * ay1 + q12 * az1 + u1;
    const float pz1 = q20 * ax1 + q21 * ay1 + q22 * az1 + u2;
    const float sc1 = s * (px1 * px1 + py1 * py1 + pz1 * pz1);

    const u64 Px0 = pk(px0, px0), Py0 = pk(py0, py0), Pz0 = pk(pz0, pz0), Sc0 = pk(sc0, sc0);
    const u64 Px1 = pk(px1, px1), Py1 = pk(py1, py1), Pz1 = pk(pz1, pz1), Sc1 = pk(sc1, sc1);

    u64 Se0 = 0ull, St0 = 0ull;   // packed (0.0f, 0.0f)
    u64 Se1 = 0ull, St1 = 0ull;

    __syncthreads();

    #pragma unroll 8
    for (int j = 0; j < 128; j++) {
        const ulonglong2 v1 = *(const ulonglong2*)(sm + j * 4);     // vx, vy
        const ulonglong2 v2 = *(const ulonglong2*)(sm + j * 4 + 2); // vz, vw

        // n0 chain
        u64 d0 = f2add(Sc0, v2.y);
        d0 = f2fma(Pz0, v2.x, d0);
        d0 = f2fma(Py0, v1.y, d0);
        d0 = f2fma(Px0, v1.x, d0);
        // n1 chain (independent)
        u64 d1 = f2add(Sc1, v2.y);
        d1 = f2fma(Pz1, v2.x, d1);
        d1 = f2fma(Py1, v1.y, d1);
        d1 = f2fma(Px1, v1.x, d1);

        float a0, b0, a1, b1;
        up(d0, a0, b0);
        up(d1, a1, b1);
        const u64 E0 = pk(ex2f(a0), ex2f(b0));
        const u64 E1 = pk(ex2f(a1), ex2f(b1));
        Se0 = f2add(Se0, E0);
        St0 = f2fma(E0, d0, St0);
        Se1 = f2add(Se1, E1);
        St1 = f2fma(E1, d1, St1);
    }

    // Write partials: one writer per (n, mchunk)
    float e0, e1, t0, t1;
    const int gbase = mchunk * 32768 + b * 4096 + nchunk * 512 + tid;
    up(Se0, e0, e1); up(St0, t0, t1);
    g_partE[gbase] = e0 + e1;
    g_partT[gbase] = t0 + t1;
    up(Se1, e0, e1); up(St1, t0, t1);
    g_partE[gbase + 256] = e0 + e1;
    g_partT[gbase + 256] = t0 + t1;
}

// Combine 16 m-chunk partials per n. Rare underflowed n's get an exact
// warp-cooperative shifted recompute. Then block-reduce to the global mean.
__global__ void __launch_bounds__(256) fape_reduce_kernel(
    const float* __restrict__ Xp,
    const float* __restrict__ Xt,
    const float* __restrict__ Rp,
    const float* __restrict__ tp,
    const float* __restrict__ Rt,
    const float* __restrict__ tt,
    const float* __restrict__ temp,
    float* __restrict__ out)
{
    const int idx = blockIdx.x * 256 + threadIdx.x;   // 0..32767 == b*4096 + n
    const int lane = threadIdx.x & 31;
    float sE = 0.0f, sT = 0.0f;
    #pragma unroll
    for (int c = 0; c < 16; c++) {
        sE += g_partE[c * 32768 + idx];
        sT += g_partT[c * 32768 + idx];
    }
    const float T = *temp;
    const float s = -LOG2E / T;
    const float invs = 1.0f / s;

    const bool bad = !(sE > 1e-30f);
    float weighted = bad ? 0.0f : invs * (sT / sE);

    // Warp-cooperative fallback for fully-underflowed n's.
    unsigned mask = __ballot_sync(0xffffffffu, bad);
    while (mask) {
        const int src = __ffs(mask) - 1;
        mask &= mask - 1;
        const int nidx = __shfl_sync(0xffffffffu, idx, src);
        const int b = nidx >> 12;

        // All lanes: transform of Xp[nidx] (broadcast loads)
        const float* Rq = Rp + b * 9;
        const float* tq = tp + b * 3;
        const float* xpn = Xp + (size_t)nidx * 3;
        const float qx = xpn[0], qy = xpn[1], qz = xpn[2];
        const float px = Rq[0] * qx + Rq[1] * qy + Rq[2] * qz + tq[0];
        const float py = Rq[3] * qx + Rq[4] * qy + Rq[5] * qz + tq[1];
        const float pz = Rq[6] * qx + Rq[7] * qy + Rq[8] * qz + tq[2];
        const float base = s * (px * px + py * py + pz * pz);

        const float* R  = Rt + b * 9;
        const float* tv = tt + b * 3;
        const float r00 = R[0], r01 = R[1], r02 = R[2];
        const float r10 = R[3], r11 = R[4], r12 = R[5];
        const float r20 = R[6], r21 = R[7], r22 = R[8];
        const float tx = tv[0], ty = tv[1], tz = tv[2];
        const float s2 = s * -2.0f;
        const float* xtb = Xt + (size_t)b * 4096 * 3;

        // Pass 1: max logit over m (warp-strided)
        float mx = -CUDART_INF_F;
        for (int m = lane; m < 4096; m += 32) {
            const float x = xtb[m * 3 + 0], y = xtb[m * 3 + 1], z = xtb[m * 3 + 2];
            const float ax = r00 * x + r01 * y + r02 * z + tx;
            const float ay = r10 * x + r11 * y + r12 * z + ty;
            const float az = r20 * x + r21 * y + r22 * z + tz;
            const float t = base + s * (ax * ax + ay * ay + az * az)
                          + s2 * (px * ax + py * ay + pz * az);
            mx = fmaxf(mx, t);
        }
        #pragma unroll
        for (int off = 16; off > 0; off >>= 1)
            mx = fmaxf(mx, __shfl_xor_sync(0xffffffffu, mx, off));

        // Pass 2: shifted sums
        float e2 = 0.0f, t2 = 0.0f;
        for (int m = lane; m < 4096; m += 32) {
            const float x = xtb[m * 3 + 0], y = xtb[m * 3 + 1], z = xtb[m * 3 + 2];
            const float ax = r00 * x + r01 * y + r02 * z + tx;
            const float ay = r10 * x + r11 * y + r12 * z + ty;
            const float az = r20 * x + r21 * y + r22 * z + tz;
            const float t = base + s * (ax * ax + ay * ay + az * az)
                          + s2 * (px * ax + py * ay + pz * az) - mx;
            const float e = ex2f(t);   // t <= 0
            e2 += e;
            t2 += e * t;
        }
        #pragma unroll
        for (int off = 16; off > 0; off >>= 1) {
            e2 += __shfl_xor_sync(0xffffffffu, e2, off);
            t2 += __shfl_xor_sync(0xffffffffu, t2, off);
        }
        if (lane == src)
            weighted = invs * (t2 / e2 + mx);
    }

    __shared__ float red[256];
    red[threadIdx.x] = weighted;
    __syncthreads();
    #pragma unroll
    for (int off = 128; off > 0; off >>= 1) {
        if (threadIdx.x < off) red[threadIdx.x] += red[threadIdx.x + off];
        __syncthreads();
    }
    if (threadIdx.x == 0)
        atomicAdd(out, red[0] * (1.0f / (8.0f * 4096.0f)));
}

extern "C" void kernel_launch(void* const* d_in, const int* in_sizes, int n_in,
                              void* d_out, int out_size) {
    const float* Xp   = (const float*)d_in[0];
    const float* Xt   = (const float*)d_in[1];
    const float* Rp   = (const float*)d_in[2];
    const float* tp   = (const float*)d_in[3];
    const float* Rt   = (const float*)d_in[4];
    const float* tt   = (const float*)d_in[5];
    const float* temp = (const float*)d_in[6];
    float* out = (float*)d_out;

    zero_out_kernel<<<1, 1>>>(out);
    fape_main_kernel<<<1024, 256>>>(Xp, Xt, Rp, tp, Rt, tt, temp);
    fape_reduce_kernel<<<128, 256>>>(Xp, Xt, Rp, tp, Rt, tt, temp, out);
}